// round 13
// baseline (speedup 1.0000x reference)
#include <cuda_runtime.h>
#include <cstdint>

// FINAL: 3x3 stride-1 pad-1 conv, 1 channel, weight = w * outer(kx,kx), kx=[den,1,den].
// x: (16,1,2048,2048) fp32 -> out same shape.
// Champion (R11): one-shot cp.async tile fill (128x32 tile, 256 thr, ~94% occ)
// with L2::256B read-burst hint. Measured at the chip's mixed r+w HBM ceiling
// (~6.0 TB/s, DRAM 75%); all pipeline/tile/store variants were neutral or worse.

#define TCOLS 128            // output cols per CTA
#define TROWS 32             // output rows per CTA
#define PITCH 136            // smem row pitch in floats (4 + 128 + 4)
#define SROWS 34             // smem rows (TROWS + 2)
#define NCHUNK (SROWS * 34)  // float4 chunks per tile (34 per row)

__global__ __launch_bounds__(256)
void conv3x3_v13(const float* __restrict__ x,
                 const float* __restrict__ w,
                 const float* __restrict__ den,
                 float* __restrict__ out,
                 int H, int W)
{
    __shared__ float tile[SROWS * PITCH];

    const int tid  = threadIdx.x;
    const int lane = tid & 31;
    const int wid  = tid >> 5;

    const int colbase = blockIdx.x * TCOLS;
    const int row0    = blockIdx.y * TROWS;
    const int b       = blockIdx.z;

    const size_t img = (size_t)H * W;
    const float* __restrict__ xb = x + (size_t)b * img;
    float*       __restrict__ ob = out + (size_t)b * img;

    // ---------------- one-shot async tile load: 34 rows x 34 float4 chunks ----------------
    // smem float f of row r  <->  gmem (row0-1+r, colbase-4+f)
    {
        const uint32_t sbase = (uint32_t)__cvta_generic_to_shared(tile);
        #pragma unroll
        for (int c2 = tid; c2 < NCHUNK; c2 += 256) {
            const int r  = c2 / 34;
            const int cc = c2 - r * 34;
            const int gy = row0 - 1 + r;
            const int gx = colbase - 4 + 4 * cc;
            const bool valid = ((unsigned)gy < (unsigned)H) & ((unsigned)gx < (unsigned)W);
            const int off = valid ? (gy * W + gx) : 0;      // clamp ptr when zfilled
            const int srcsize = valid ? 16 : 0;
            const uint32_t daddr = sbase + (uint32_t)(r * PITCH + 4 * cc) * 4u;
            asm volatile("cp.async.cg.shared.global.L2::256B [%0], [%1], 16, %2;"
                         :: "r"(daddr), "l"(xb + off), "r"(srcsize));
        }
        asm volatile("cp.async.commit_group;");
    }

    // effective 3x3 weights (overlaps with loads in flight)
    const float d = den[0];
    const float kv[3] = {d, 1.0f, d};
    float k[9];
    #pragma unroll
    for (int i = 0; i < 3; i++)
        #pragma unroll
        for (int j = 0; j < 3; j++)
            k[i * 3 + j] = __ldg(&w[i * 3 + j]) * kv[i] * kv[j];

    asm volatile("cp.async.wait_group 0;");
    __syncthreads();

    // ---------------- compute: warp wid -> output rows [4w, 4w+4) ----------------
    const int base_f = 4 * lane;
    auto ldrow = [&](int r, float* s) {
        const float* p = &tile[r * PITCH + base_f];
        const float4 v = *reinterpret_cast<const float4*>(p + 4);
        s[0] = p[3]; s[1] = v.x; s[2] = v.y; s[3] = v.z; s[4] = v.w; s[5] = p[8];
    };

    float s0[6], s1[6], s2[6];
    const int lr0 = 4 * wid;        // local smem row of first needed input row
    ldrow(lr0,     s0);
    ldrow(lr0 + 1, s1);

    float* ro = ob + (size_t)(row0 + lr0) * W + colbase + base_f;

    #pragma unroll
    for (int oo = 0; oo < 4; oo++) {
        ldrow(lr0 + 2 + oo, s2);

        float a0 = 0.f, a1 = 0.f, a2 = 0.f, a3 = 0.f;
        #pragma unroll
        for (int i = 0; i < 3; i++) {
            const float* s = (i == 0) ? s0 : (i == 1) ? s1 : s2;
            const float w0 = k[3 * i], w1 = k[3 * i + 1], w2 = k[3 * i + 2];
            a0 = fmaf(w0, s[0], fmaf(w1, s[1], fmaf(w2, s[2], a0)));
            a1 = fmaf(w0, s[1], fmaf(w1, s[2], fmaf(w2, s[3], a1)));
            a2 = fmaf(w0, s[2], fmaf(w1, s[3], fmaf(w2, s[4], a2)));
            a3 = fmaf(w0, s[3], fmaf(w1, s[4], fmaf(w2, s[5], a3)));
        }
        *reinterpret_cast<float4*>(ro) = make_float4(a0, a1, a2, a3);
        ro += W;

        #pragma unroll
        for (int i = 0; i < 6; i++) { s0[i] = s1[i]; s1[i] = s2[i]; }
    }
}

extern "C" void kernel_launch(void* const* d_in, const int* in_sizes, int n_in,
                              void* d_out, int out_size)
{
    const float* x   = (const float*)d_in[0];   // (16,1,2048,2048) fp32
    const float* w   = (const float*)d_in[1];   // (1,1,3,3) fp32
    const float* den = (const float*)d_in[2];   // (1,) fp32
    float* out = (float*)d_out;

    const int B = 16, H = 2048, W = 2048;
    (void)in_sizes; (void)n_in; (void)out_size;

    dim3 grid(W / TCOLS, H / TROWS, B);   // 16 x 64 x 16 = 16384 CTAs
    dim3 block(256);
    conv3x3_v13<<<grid, block>>>(x, w, den, out, H, W);
}

// round 14
// speedup vs baseline: 1.0170x; 1.0170x over previous
#include <cuda_runtime.h>
#include <cstdint>

// FINAL (locked champion, = R11): 3x3 stride-1 pad-1 conv, 1 channel,
// weight = w * outer(kx,kx), kx=[den,1,den].
// x: (16,1,2048,2048) fp32 -> out same shape.
// One-shot cp.async tile fill (128x32 tile, 256 thr, ~93% occ) with L2::256B
// read-burst hint. Runs at the chip's mixed r+w HBM ceiling (~6.0 TB/s,
// DRAM 75%); 8 structural variants (pipelining, tile geometry, bulk-DMA,
// store policy) all measured neutral or worse.

#define TCOLS 128            // output cols per CTA
#define TROWS 32             // output rows per CTA
#define PITCH 136            // smem row pitch in floats (4 + 128 + 4)
#define SROWS 34             // smem rows (TROWS + 2)
#define NCHUNK (SROWS * 34)  // float4 chunks per tile (34 per row)

__global__ __launch_bounds__(256)
void conv3x3_champ(const float* __restrict__ x,
                   const float* __restrict__ w,
                   const float* __restrict__ den,
                   float* __restrict__ out,
                   int H, int W)
{
    __shared__ float tile[SROWS * PITCH];

    const int tid  = threadIdx.x;
    const int lane = tid & 31;
    const int wid  = tid >> 5;

    const int colbase = blockIdx.x * TCOLS;
    const int row0    = blockIdx.y * TROWS;
    const int b       = blockIdx.z;

    const size_t img = (size_t)H * W;
    const float* __restrict__ xb = x + (size_t)b * img;
    float*       __restrict__ ob = out + (size_t)b * img;

    // ---------------- one-shot async tile load: 34 rows x 34 float4 chunks ----------------
    // smem float f of row r  <->  gmem (row0-1+r, colbase-4+f)
    {
        const uint32_t sbase = (uint32_t)__cvta_generic_to_shared(tile);
        #pragma unroll
        for (int c2 = tid; c2 < NCHUNK; c2 += 256) {
            const int r  = c2 / 34;
            const int cc = c2 - r * 34;
            const int gy = row0 - 1 + r;
            const int gx = colbase - 4 + 4 * cc;
            const bool valid = ((unsigned)gy < (unsigned)H) & ((unsigned)gx < (unsigned)W);
            const int off = valid ? (gy * W + gx) : 0;      // clamp ptr when zfilled
            const int srcsize = valid ? 16 : 0;
            const uint32_t daddr = sbase + (uint32_t)(r * PITCH + 4 * cc) * 4u;
            asm volatile("cp.async.cg.shared.global.L2::256B [%0], [%1], 16, %2;"
                         :: "r"(daddr), "l"(xb + off), "r"(srcsize));
        }
        asm volatile("cp.async.commit_group;");
    }

    // effective 3x3 weights (overlaps with loads in flight)
    const float d = den[0];
    const float kv[3] = {d, 1.0f, d};
    float k[9];
    #pragma unroll
    for (int i = 0; i < 3; i++)
        #pragma unroll
        for (int j = 0; j < 3; j++)
            k[i * 3 + j] = __ldg(&w[i * 3 + j]) * kv[i] * kv[j];

    asm volatile("cp.async.wait_group 0;");
    __syncthreads();

    // ---------------- compute: warp wid -> output rows [4w, 4w+4) ----------------
    const int base_f = 4 * lane;
    auto ldrow = [&](int r, float* s) {
        const float* p = &tile[r * PITCH + base_f];
        const float4 v = *reinterpret_cast<const float4*>(p + 4);
        s[0] = p[3]; s[1] = v.x; s[2] = v.y; s[3] = v.z; s[4] = v.w; s[5] = p[8];
    };

    float s0[6], s1[6], s2[6];
    const int lr0 = 4 * wid;        // local smem row of first needed input row
    ldrow(lr0,     s0);
    ldrow(lr0 + 1, s1);

    float* ro = ob + (size_t)(row0 + lr0) * W + colbase + base_f;

    #pragma unroll
    for (int oo = 0; oo < 4; oo++) {
        ldrow(lr0 + 2 + oo, s2);

        float a0 = 0.f, a1 = 0.f, a2 = 0.f, a3 = 0.f;
        #pragma unroll
        for (int i = 0; i < 3; i++) {
            const float* s = (i == 0) ? s0 : (i == 1) ? s1 : s2;
            const float w0 = k[3 * i], w1 = k[3 * i + 1], w2 = k[3 * i + 2];
            a0 = fmaf(w0, s[0], fmaf(w1, s[1], fmaf(w2, s[2], a0)));
            a1 = fmaf(w0, s[1], fmaf(w1, s[2], fmaf(w2, s[3], a1)));
            a2 = fmaf(w0, s[2], fmaf(w1, s[3], fmaf(w2, s[4], a2)));
            a3 = fmaf(w0, s[3], fmaf(w1, s[4], fmaf(w2, s[5], a3)));
        }
        *reinterpret_cast<float4*>(ro) = make_float4(a0, a1, a2, a3);
        ro += W;

        #pragma unroll
        for (int i = 0; i < 6; i++) { s0[i] = s1[i]; s1[i] = s2[i]; }
    }
}

extern "C" void kernel_launch(void* const* d_in, const int* in_sizes, int n_in,
                              void* d_out, int out_size)
{
    const float* x   = (const float*)d_in[0];   // (16,1,2048,2048) fp32
    const float* w   = (const float*)d_in[1];   // (1,1,3,3) fp32
    const float* den = (const float*)d_in[2];   // (1,) fp32
    float* out = (float*)d_out;

    const int B = 16, H = 2048, W = 2048;
    (void)in_sizes; (void)n_in; (void)out_size;

    dim3 grid(W / TCOLS, H / TROWS, B);   // 16 x 64 x 16 = 16384 CTAs
    dim3 block(256);
    conv3x3_champ<<<grid, block>>>(x, w, den, out, H, W);
}

// round 15
// speedup vs baseline: 1.0251x; 1.0080x over previous
#include <cuda_runtime.h>
#include <cstdint>

// FINAL (locked champion): 3x3 stride-1 pad-1 conv, 1 channel,
// weight = w * outer(kx,kx), kx=[den,1,den].
// x: (16,1,2048,2048) fp32 -> out same shape.
// One-shot cp.async tile fill (128x32 tile, 256 thr, ~93% occ) with L2::256B
// read-burst hint. Runs at the chip's mixed r+w HBM ceiling (~6.0 TB/s,
// DRAM ~75%); verified across 4 samples; 8 structural variants (pipelining,
// tile geometry, bulk-DMA, store policy) all measured neutral or worse.

#define TCOLS 128            // output cols per CTA
#define TROWS 32             // output rows per CTA
#define PITCH 136            // smem row pitch in floats (4 + 128 + 4)
#define SROWS 34             // smem rows (TROWS + 2)
#define NCHUNK (SROWS * 34)  // float4 chunks per tile (34 per row)

__global__ __launch_bounds__(256)
void conv3x3_champ(const float* __restrict__ x,
                   const float* __restrict__ w,
                   const float* __restrict__ den,
                   float* __restrict__ out,
                   int H, int W)
{
    __shared__ float tile[SROWS * PITCH];

    const int tid  = threadIdx.x;
    const int lane = tid & 31;
    const int wid  = tid >> 5;

    const int colbase = blockIdx.x * TCOLS;
    const int row0    = blockIdx.y * TROWS;
    const int b       = blockIdx.z;

    const size_t img = (size_t)H * W;
    const float* __restrict__ xb = x + (size_t)b * img;
    float*       __restrict__ ob = out + (size_t)b * img;

    // ---------------- one-shot async tile load: 34 rows x 34 float4 chunks ----------------
    // smem float f of row r  <->  gmem (row0-1+r, colbase-4+f)
    {
        const uint32_t sbase = (uint32_t)__cvta_generic_to_shared(tile);
        #pragma unroll
        for (int c2 = tid; c2 < NCHUNK; c2 += 256) {
            const int r  = c2 / 34;
            const int cc = c2 - r * 34;
            const int gy = row0 - 1 + r;
            const int gx = colbase - 4 + 4 * cc;
            const bool valid = ((unsigned)gy < (unsigned)H) & ((unsigned)gx < (unsigned)W);
            const int off = valid ? (gy * W + gx) : 0;      // clamp ptr when zfilled
            const int srcsize = valid ? 16 : 0;
            const uint32_t daddr = sbase + (uint32_t)(r * PITCH + 4 * cc) * 4u;
            asm volatile("cp.async.cg.shared.global.L2::256B [%0], [%1], 16, %2;"
                         :: "r"(daddr), "l"(xb + off), "r"(srcsize));
        }
        asm volatile("cp.async.commit_group;");
    }

    // effective 3x3 weights (overlaps with loads in flight)
    const float d = den[0];
    const float kv[3] = {d, 1.0f, d};
    float k[9];
    #pragma unroll
    for (int i = 0; i < 3; i++)
        #pragma unroll
        for (int j = 0; j < 3; j++)
            k[i * 3 + j] = __ldg(&w[i * 3 + j]) * kv[i] * kv[j];

    asm volatile("cp.async.wait_group 0;");
    __syncthreads();

    // ---------------- compute: warp wid -> output rows [4w, 4w+4) ----------------
    const int base_f = 4 * lane;
    auto ldrow = [&](int r, float* s) {
        const float* p = &tile[r * PITCH + base_f];
        const float4 v = *reinterpret_cast<const float4*>(p + 4);
        s[0] = p[3]; s[1] = v.x; s[2] = v.y; s[3] = v.z; s[4] = v.w; s[5] = p[8];
    };

    float s0[6], s1[6], s2[6];
    const int lr0 = 4 * wid;        // local smem row of first needed input row
    ldrow(lr0,     s0);
    ldrow(lr0 + 1, s1);

    float* ro = ob + (size_t)(row0 + lr0) * W + colbase + base_f;

    #pragma unroll
    for (int oo = 0; oo < 4; oo++) {
        ldrow(lr0 + 2 + oo, s2);

        float a0 = 0.f, a1 = 0.f, a2 = 0.f, a3 = 0.f;
        #pragma unroll
        for (int i = 0; i < 3; i++) {
            const float* s = (i == 0) ? s0 : (i == 1) ? s1 : s2;
            const float w0 = k[3 * i], w1 = k[3 * i + 1], w2 = k[3 * i + 2];
            a0 = fmaf(w0, s[0], fmaf(w1, s[1], fmaf(w2, s[2], a0)));
            a1 = fmaf(w0, s[1], fmaf(w1, s[2], fmaf(w2, s[3], a1)));
            a2 = fmaf(w0, s[2], fmaf(w1, s[3], fmaf(w2, s[4], a2)));
            a3 = fmaf(w0, s[3], fmaf(w1, s[4], fmaf(w2, s[5], a3)));
        }
        *reinterpret_cast<float4*>(ro) = make_float4(a0, a1, a2, a3);
        ro += W;

        #pragma unroll
        for (int i = 0; i < 6; i++) { s0[i] = s1[i]; s1[i] = s2[i]; }
    }
}

extern "C" void kernel_launch(void* const* d_in, const int* in_sizes, int n_in,
                              void* d_out, int out_size)
{
    const float* x   = (const float*)d_in[0];   // (16,1,2048,2048) fp32
    const float* w   = (const float*)d_in[1];   // (1,1,3,3) fp32
    const float* den = (const float*)d_in[2];   // (1,) fp32
    float* out = (float*)d_out;

    const int B = 16, H = 2048, W = 2048;
    (void)in_sizes; (void)n_in; (void)out_size;

    dim3 grid(W / TCOLS, H / TROWS, B);   // 16 x 64 x 16 = 16384 CTAs
    dim3 block(256);
    conv3x3_champ<<<grid, block>>>(x, w, den, out, H, W);
}